// round 10
// baseline (speedup 1.0000x reference)
#include <cuda_runtime.h>
#include <math.h>

#define S_LEN 4096
#define D_MODEL 1024
#define NH 16
#define HD 64

// Scratch (allocation-free requirement -> __device__ globals)
__device__ float g_qkv[(size_t)S_LEN * 3 * D_MODEL];    // [S][3D], tf32-rounded
__device__ float g_ctx[(size_t)S_LEN * D_MODEL];        // [S][D], tf32-rounded
__device__ float g_xc[(size_t)S_LEN * D_MODEL];         // x, tf32-rounded
__device__ float g_wqkv[(size_t)D_MODEL * 3 * D_MODEL]; // [D][3D], tf32-rounded
__device__ float g_wproj[(size_t)D_MODEL * D_MODEL];    // [D][D], tf32-rounded

// ---------------------------------------------------------------------------
// tf32 helpers
// ---------------------------------------------------------------------------
__device__ __forceinline__ unsigned f2tf(float f) {
    unsigned u;
    asm("cvt.rna.tf32.f32 %0, %1;" : "=r"(u) : "f"(f));
    return u;
}
__device__ __forceinline__ float tf32r(float f) { return __uint_as_float(f2tf(f)); }

__device__ __forceinline__ void mma8(float* d, const unsigned* a, const unsigned* b) {
    asm volatile("mma.sync.aligned.m16n8k8.row.col.f32.tf32.tf32.f32 "
        "{%0,%1,%2,%3}, {%4,%5,%6,%7}, {%8,%9}, {%0,%1,%2,%3};"
        : "+f"(d[0]), "+f"(d[1]), "+f"(d[2]), "+f"(d[3])
        : "r"(a[0]), "r"(a[1]), "r"(a[2]), "r"(a[3]), "r"(b[0]), "r"(b[1]));
}

// One-time elementwise tf32 rounding
__global__ void conv_tf32_kernel(const float4* __restrict__ src, float4* __restrict__ dst, int n4) {
    int i = blockIdx.x * blockDim.x + threadIdx.x;
    if (i < n4) {
        float4 v = src[i];
        dst[i] = make_float4(tf32r(v.x), tf32r(v.y), tf32r(v.z), tf32r(v.w));
    }
}

// ---------------------------------------------------------------------------
// GEMM: C[M,N] = A[M,K] @ B[K,N] + bias  (pre-tf32 in, tf32 mma)
// 128x128 block, BK=32, 256 threads (8 warps, 4x2), warp tile 32x64.
// Double-buffered smem, staged A-then-B register prefetch, 1 barrier/iter.
// No conversions in the hot loop (all inputs pre-rounded).
// ---------------------------------------------------------------------------
#define BM 128
#define BN 128
#define BK 32
#define ASTR 36    // 36%32=4: frag banks 4g+t distinct over warp
#define BSTR 136   // 136%32=8: frag banks 8t+g distinct over warp
#define A_TILE (BM * ASTR)   // 4608
#define B_TILE (BK * BSTR)   // 4352

__global__ __launch_bounds__(256, 2) void gemm_tf32_kernel(
    const float* __restrict__ A, const float* __restrict__ B,
    const float* __restrict__ bias, float* __restrict__ C,
    int M, int N, int K, int cvt_out)
{
    extern __shared__ float gsm[];
    float* As = gsm;                 // [2][BM][ASTR]
    float* Bs = gsm + 2 * A_TILE;    // [2][BK][BSTR]

    const int tid  = threadIdx.x;
    const int warp = tid >> 5, lane = tid & 31;
    const int g = lane >> 2, t = lane & 3;
    const int wm = (warp & 3) * 32;
    const int wn = (warp >> 2) * 64;
    const int m0 = blockIdx.y * BM, n0 = blockIdx.x * BN;

    // Loader slots: A: row = (tid>>3)+32p, cols aq..aq+3 ; B: row = warp+8p, cols bcg..+3
    const int arow = tid >> 3, aq = (tid & 7) << 2;
    const int brow = tid >> 5, bcg = (tid & 31) << 2;

    float acc[2][8][4];
    #pragma unroll
    for (int mt = 0; mt < 2; ++mt)
        #pragma unroll
        for (int nt = 0; nt < 8; ++nt)
            #pragma unroll
            for (int i = 0; i < 4; ++i) acc[mt][nt][i] = 0.f;

    float4 ra[4], rb[4];

    // prologue: tile 0 -> buf 0
    #pragma unroll
    for (int p = 0; p < 4; ++p) {
        ra[p] = *(const float4*)(A + (size_t)(m0 + arow + 32 * p) * K + aq);
        rb[p] = *(const float4*)(B + (size_t)(brow + 8 * p) * N + n0 + bcg);
    }
    #pragma unroll
    for (int p = 0; p < 4; ++p) {
        *(float4*)&As[(arow + 32 * p) * ASTR + aq] = ra[p];
        *(float4*)&Bs[(brow + 8 * p) * BSTR + bcg] = rb[p];
    }
    __syncthreads();

    int cur = 0;
    for (int k0 = 0; k0 < K; k0 += BK) {
        const bool hn = (k0 + BK) < K;
        const int kk = k0 + BK;

        if (hn) {
            #pragma unroll
            for (int p = 0; p < 4; ++p)
                ra[p] = *(const float4*)(A + (size_t)(m0 + arow + 32 * p) * K + kk + aq);
        }

        const unsigned* Ac = (const unsigned*)(As + cur * A_TILE);
        const unsigned* Bc = (const unsigned*)(Bs + cur * B_TILE);

        #pragma unroll
        for (int c = 0; c < 2; ++c) {
            unsigned a[2][4], b[8][2];
            #pragma unroll
            for (int mt = 0; mt < 2; ++mt) {
                int r = wm + mt * 16;
                a[mt][0] = Ac[(r + g) * ASTR + c * 8 + t];
                a[mt][1] = Ac[(r + g + 8) * ASTR + c * 8 + t];
                a[mt][2] = Ac[(r + g) * ASTR + c * 8 + t + 4];
                a[mt][3] = Ac[(r + g + 8) * ASTR + c * 8 + t + 4];
            }
            #pragma unroll
            for (int nt = 0; nt < 8; ++nt) {
                b[nt][0] = Bc[(c * 8 + t) * BSTR + wn + nt * 8 + g];
                b[nt][1] = Bc[(c * 8 + t + 4) * BSTR + wn + nt * 8 + g];
            }
            #pragma unroll
            for (int mt = 0; mt < 2; ++mt)
                #pragma unroll
                for (int nt = 0; nt < 8; ++nt)
                    mma8(acc[mt][nt], a[mt], b[nt]);
        }

        if (hn) {
            int nb = cur ^ 1;
            #pragma unroll
            for (int p = 0; p < 4; ++p) {
                *(float4*)&As[nb * A_TILE + (arow + 32 * p) * ASTR + aq] = ra[p];
                rb[p] = *(const float4*)(B + (size_t)(kk + brow + 8 * p) * N + n0 + bcg);
            }
        }

        #pragma unroll
        for (int c = 2; c < 4; ++c) {
            unsigned a[2][4], b[8][2];
            #pragma unroll
            for (int mt = 0; mt < 2; ++mt) {
                int r = wm + mt * 16;
                a[mt][0] = Ac[(r + g) * ASTR + c * 8 + t];
                a[mt][1] = Ac[(r + g + 8) * ASTR + c * 8 + t];
                a[mt][2] = Ac[(r + g) * ASTR + c * 8 + t + 4];
                a[mt][3] = Ac[(r + g + 8) * ASTR + c * 8 + t + 4];
            }
            #pragma unroll
            for (int nt = 0; nt < 8; ++nt) {
                b[nt][0] = Bc[(c * 8 + t) * BSTR + wn + nt * 8 + g];
                b[nt][1] = Bc[(c * 8 + t + 4) * BSTR + wn + nt * 8 + g];
            }
            #pragma unroll
            for (int mt = 0; mt < 2; ++mt)
                #pragma unroll
                for (int nt = 0; nt < 8; ++nt)
                    mma8(acc[mt][nt], a[mt], b[nt]);
        }

        if (hn) {
            int nb = cur ^ 1;
            #pragma unroll
            for (int p = 0; p < 4; ++p)
                *(float4*)&Bs[nb * B_TILE + (brow + 8 * p) * BSTR + bcg] = rb[p];
            __syncthreads();
            cur = nb;
        }
    }

    #pragma unroll
    for (int mt = 0; mt < 2; ++mt) {
        int row = m0 + wm + mt * 16 + g;
        #pragma unroll
        for (int nt = 0; nt < 8; ++nt) {
            int col = n0 + wn + nt * 8 + 2 * t;
            float b0 = bias[col], b1 = bias[col + 1];
            float v0 = acc[mt][nt][0] + b0, v1 = acc[mt][nt][1] + b1;
            float v2 = acc[mt][nt][2] + b0, v3 = acc[mt][nt][3] + b1;
            if (cvt_out) { v0 = tf32r(v0); v1 = tf32r(v1); v2 = tf32r(v2); v3 = tf32r(v3); }
            *(float2*)(C + (size_t)row * N + col)       = make_float2(v0, v1);
            *(float2*)(C + (size_t)(row + 8) * N + col) = make_float2(v2, v3);
        }
    }
}

// ---------------------------------------------------------------------------
// Flash attention, tf32 mma. Block = (head, 128-query tile), 8 warps.
// Double-buffered K/V (no conversions: qkv pre-rounded); P via quad shuffles.
// ---------------------------------------------------------------------------
#define BQ 128
#define BKV 64
#define QSTR 68   // 68%32=4: banks 4g+t conflict-free
#define KSTR 68
#define VSTR 72   // 72%32=8: banks 8t+g conflict-free
#define Q_TILE (BQ * QSTR)    // 8704
#define K_TILE (BKV * KSTR)   // 4352
#define V_TILE (BKV * VSTR)   // 4608

__global__ __launch_bounds__(256, 2) void attn_tf32_kernel(
    const float* __restrict__ qkv, float* __restrict__ ctx)
{
    extern __shared__ float smem[];
    float* Qs = smem;                 // [128][QSTR]
    float* Ks = smem + Q_TILE;        // [2][64][KSTR]
    float* Vs = Ks + 2 * K_TILE;      // [2][64][VSTR]

    const int h  = blockIdx.y;
    const int qt = (int)gridDim.x - 1 - (int)blockIdx.x;   // heavy tiles first
    const int q0 = qt * BQ;
    const int tid = threadIdx.x;
    const int warp = tid >> 5, lane = tid & 31;
    const int g = lane >> 2, t = lane & 3;
    const int wm = warp * 16;

    const float* kb = qkv + D_MODEL + h * HD;
    const float* vb = qkv + 2 * D_MODEL + h * HD;

    // Load Q tile (pre-rounded; *0.125 is exact so no re-round needed)
    const float* qb = qkv + (size_t)q0 * (3 * D_MODEL) + h * HD;
    for (int idx = tid; idx < BQ * 16; idx += 256) {
        int row = idx >> 4, dq = (idx & 15) << 2;
        float4 v = *(const float4*)(qb + (size_t)row * (3 * D_MODEL) + dq);
        *(float4*)&Qs[row * QSTR + dq] =
            make_float4(v.x * 0.125f, v.y * 0.125f, v.z * 0.125f, v.w * 0.125f);
    }

    float m_[2] = {-1e30f, -1e30f};
    float l_[2] = {0.f, 0.f};
    float o[8][4];
    #pragma unroll
    for (int nt = 0; nt < 8; ++nt)
        #pragma unroll
        for (int i = 0; i < 4; ++i) o[nt][i] = 0.f;

    const int nkt = 2 * qt + 2;
    float4 rk[4], rv[4];

    // prologue: K/V tile 0 -> buf 0
    #pragma unroll
    for (int i = 0; i < 4; ++i) {
        int idx = tid + i * 256;
        int row = idx >> 4, dq = (idx & 15) << 2;
        rk[i] = *(const float4*)(kb + (size_t)row * (3 * D_MODEL) + dq);
        rv[i] = *(const float4*)(vb + (size_t)row * (3 * D_MODEL) + dq);
    }
    #pragma unroll
    for (int i = 0; i < 4; ++i) {
        int idx = tid + i * 256;
        int row = idx >> 4, dq = (idx & 15) << 2;
        *(float4*)&Ks[row * KSTR + dq] = rk[i];
        *(float4*)&Vs[row * VSTR + dq] = rv[i];
    }
    __syncthreads();

    int cur = 0;
    const int src0 = (lane & ~3) | (t >> 1);   // owner quad-lane of P col (k%8)=t
    const bool odd = (t & 1);

    for (int kt = 0; kt < nkt; ++kt) {
        const bool hn = (kt + 1) < nkt;
        const bool active = (kt * BKV <= q0 + wm + 15);
        float s[8][4];

        if (hn) {
            #pragma unroll
            for (int i = 0; i < 4; ++i) {
                int idx = tid + i * 256;
                int row = idx >> 4, dq = (idx & 15) << 2;
                rk[i] = *(const float4*)(kb + (size_t)((kt + 1) * BKV + row) * (3 * D_MODEL) + dq);
            }
        }

        const unsigned* Kc = (const unsigned*)(Ks + cur * K_TILE);
        const unsigned* Vc = (const unsigned*)(Vs + cur * V_TILE);

        if (active) {
            // S = Q K^T   (16 x 64 per warp)
            #pragma unroll
            for (int nt = 0; nt < 8; ++nt)
                #pragma unroll
                for (int i = 0; i < 4; ++i) s[nt][i] = 0.f;

            const unsigned* Qu = (const unsigned*)Qs;
            #pragma unroll
            for (int ks = 0; ks < 8; ++ks) {
                unsigned a[4];
                a[0] = Qu[(wm + g) * QSTR + ks * 8 + t];
                a[1] = Qu[(wm + g + 8) * QSTR + ks * 8 + t];
                a[2] = Qu[(wm + g) * QSTR + ks * 8 + t + 4];
                a[3] = Qu[(wm + g + 8) * QSTR + ks * 8 + t + 4];
                #pragma unroll
                for (int nt = 0; nt < 8; ++nt) {
                    unsigned b[2];
                    b[0] = Kc[(nt * 8 + g) * KSTR + ks * 8 + t];
                    b[1] = Kc[(nt * 8 + g) * KSTR + ks * 8 + t + 4];
                    mma8(s[nt], a, b);
                }
            }

            // Causal mask (only diagonal k-tiles mask anything)
            if (kt >= 2 * qt) {
                int r0 = q0 + wm + g;
                #pragma unroll
                for (int nt = 0; nt < 8; ++nt) {
                    int col = kt * BKV + nt * 8 + 2 * t;
                    if (col     > r0)     s[nt][0] = -1e30f;
                    if (col + 1 > r0)     s[nt][1] = -1e30f;
                    if (col     > r0 + 8) s[nt][2] = -1e30f;
                    if (col + 1 > r0 + 8) s[nt][3] = -1e30f;
                }
            }

            // Online softmax (rows g, g+8; quad reduction over 4 lanes)
            #pragma unroll
            for (int r = 0; r < 2; ++r) {
                float tm = -1e30f;
                #pragma unroll
                for (int nt = 0; nt < 8; ++nt)
                    tm = fmaxf(tm, fmaxf(s[nt][2 * r], s[nt][2 * r + 1]));
                tm = fmaxf(tm, __shfl_xor_sync(0xffffffffu, tm, 1));
                tm = fmaxf(tm, __shfl_xor_sync(0xffffffffu, tm, 2));
                float mn = fmaxf(m_[r], tm);
                float rs = 0.f;
                #pragma unroll
                for (int nt = 0; nt < 8; ++nt) {
                    float p0 = __expf(s[nt][2 * r] - mn);
                    float p1 = __expf(s[nt][2 * r + 1] - mn);
                    s[nt][2 * r] = p0; s[nt][2 * r + 1] = p1;
                    rs += p0 + p1;
                }
                rs += __shfl_xor_sync(0xffffffffu, rs, 1);
                rs += __shfl_xor_sync(0xffffffffu, rs, 2);
                float alpha = __expf(m_[r] - mn);
                l_[r] = l_[r] * alpha + rs;
                #pragma unroll
                for (int nt = 0; nt < 8; ++nt) {
                    o[nt][2 * r] *= alpha; o[nt][2 * r + 1] *= alpha;
                }
                m_[r] = mn;
            }
        }

        if (hn) {
            int nb = cur ^ 1;
            #pragma unroll
            for (int i = 0; i < 4; ++i) {
                int idx = tid + i * 256;
                int row = idx >> 4, dq = (idx & 15) << 2;
                *(float4*)&Ks[nb * K_TILE + row * KSTR + dq] = rk[i];
                rv[i] = *(const float4*)(vb + (size_t)((kt + 1) * BKV + row) * (3 * D_MODEL) + dq);
            }
        }

        if (active) {
            // O += P V : P fragment gathered from s regs via quad shuffles.
            #pragma unroll
            for (int ks = 0; ks < 8; ++ks) {
                float x0 = __shfl_sync(0xffffffffu, s[ks][0], src0);
                float x1 = __shfl_sync(0xffffffffu, s[ks][1], src0);
                float y0 = __shfl_sync(0xffffffffu, s[ks][2], src0);
                float y1 = __shfl_sync(0xffffffffu, s[ks][3], src0);
                float x2 = __shfl_sync(0xffffffffu, s[ks][0], src0 + 2);
                float x3 = __shfl_sync(0xffffffffu, s[ks][1], src0 + 2);
                float y2 = __shfl_sync(0xffffffffu, s[ks][2], src0 + 2);
                float y3 = __shfl_sync(0xffffffffu, s[ks][3], src0 + 2);
                unsigned a[4];
                a[0] = f2tf(odd ? x1 : x0);
                a[1] = f2tf(odd ? y1 : y0);
                a[2] = f2tf(odd ? x3 : x2);
                a[3] = f2tf(odd ? y3 : y2);
                #pragma unroll
                for (int nt = 0; nt < 8; ++nt) {
                    unsigned b[2];
                    b[0] = Vc[(ks * 8 + t) * VSTR + nt * 8 + g];
                    b[1] = Vc[(ks * 8 + t + 4) * VSTR + nt * 8 + g];
                    mma8(o[nt], a, b);
                }
            }
        }

        if (hn) {
            int nb = cur ^ 1;
            #pragma unroll
            for (int i = 0; i < 4; ++i) {
                int idx = tid + i * 256;
                int row = idx >> 4, dq = (idx & 15) << 2;
                *(float4*)&Vs[nb * V_TILE + row * VSTR + dq] = rv[i];
            }
            __syncthreads();
            cur = nb;
        }
    }

    // Epilogue: normalize, tf32-round (proj GEMM consumes), write ctx[q][h*64+d]
    float inv0 = 1.f / l_[0], inv1 = 1.f / l_[1];
    float* ob = ctx + (size_t)(q0 + wm) * D_MODEL + h * HD;
    #pragma unroll
    for (int nt = 0; nt < 8; ++nt) {
        int col = nt * 8 + 2 * t;
        *(float2*)(ob + (size_t)g * D_MODEL + col) =
            make_float2(tf32r(o[nt][0] * inv0), tf32r(o[nt][1] * inv0));
        *(float2*)(ob + (size_t)(g + 8) * D_MODEL + col) =
            make_float2(tf32r(o[nt][2] * inv1), tf32r(o[nt][3] * inv1));
    }
}

// ---------------------------------------------------------------------------
// Launch
// ---------------------------------------------------------------------------
extern "C" void kernel_launch(void* const* d_in, const int* in_sizes, int n_in,
                              void* d_out, int out_size)
{
    const float* x      = (const float*)d_in[0];
    const float* w_qkv  = (const float*)d_in[1];
    const float* b_qkv  = (const float*)d_in[2];
    const float* w_proj = (const float*)d_in[3];
    const float* b_proj = (const float*)d_in[4];
    float* out = (float*)d_out;

    float *qkv_p, *ctx_p, *xc_p, *wqkv_p, *wproj_p;
    cudaGetSymbolAddress((void**)&qkv_p, g_qkv);
    cudaGetSymbolAddress((void**)&ctx_p, g_ctx);
    cudaGetSymbolAddress((void**)&xc_p, g_xc);
    cudaGetSymbolAddress((void**)&wqkv_p, g_wqkv);
    cudaGetSymbolAddress((void**)&wproj_p, g_wproj);

    const int gemm_smem = (2 * A_TILE + 2 * B_TILE) * (int)sizeof(float);            // 71680
    const int attn_smem = (Q_TILE + 2 * K_TILE + 2 * V_TILE) * (int)sizeof(float);   // 106496
    cudaFuncSetAttribute(gemm_tf32_kernel, cudaFuncAttributeMaxDynamicSharedMemorySize, gemm_smem);
    cudaFuncSetAttribute(attn_tf32_kernel, cudaFuncAttributeMaxDynamicSharedMemorySize, attn_smem);

    // 0) one-time tf32 rounding of x and weights (layouts unchanged)
    conv_tf32_kernel<<<(S_LEN * D_MODEL / 4 + 255) / 256, 256>>>(
        (const float4*)x, (float4*)xc_p, S_LEN * D_MODEL / 4);
    conv_tf32_kernel<<<(3 * D_MODEL * D_MODEL / 4 + 255) / 256, 256>>>(
        (const float4*)w_qkv, (float4*)wqkv_p, 3 * D_MODEL * D_MODEL / 4);
    conv_tf32_kernel<<<(D_MODEL * D_MODEL / 4 + 255) / 256, 256>>>(
        (const float4*)w_proj, (float4*)wproj_p, D_MODEL * D_MODEL / 4);

    // 1) qkv = x @ w_qkv + b_qkv  (tf32-rounded output)
    gemm_tf32_kernel<<<dim3(3 * D_MODEL / BN, S_LEN / BM), 256, gemm_smem>>>(
        xc_p, wqkv_p, b_qkv, qkv_p, S_LEN, 3 * D_MODEL, D_MODEL, 1);

    // 2) causal flash attention -> ctx (tf32-rounded output)
    attn_tf32_kernel<<<dim3(S_LEN / BQ, NH), 256, attn_smem>>>(qkv_p, ctx_p);

    // 3) out = ctx @ w_proj + b_proj (plain fp32 output)
    gemm_tf32_kernel<<<dim3(D_MODEL / BN, S_LEN / BM), 256, gemm_smem>>>(
        ctx_p, wproj_p, b_proj, out, S_LEN, D_MODEL, D_MODEL, 0);
}